// round 13
// baseline (speedup 1.0000x reference)
#include <cuda_runtime.h>
#include <math.h>

typedef unsigned long long ull;

#define NMAX 524288

// ---------------- device-global scratch ----------------
__device__ __align__(16) float g_T[92 * NMAX];     // ifrd transposed: [feat][pt]
__device__ __align__(16) float g_voxT[8 * NMAX];   // vox transposed
__device__ __align__(16) float g_X[64 * NMAX];     // x_relu SoA [j][pt]
__device__ __align__(16) float g_VIF[16 * NMAX];   // img_feat (vif[8..23]) SoA

// ---------------- weight layout ----------------
// A section (trunk kernel)
#define A_GLOB_WT 0       // [57][32]
#define A_GLOB_B  1824
#define A_AGGW    1856
#define A_FC_WT   1888    // [32][16]
#define A_FC_B    2400
#define A_LR0_WT  2416    // [24][64]
#define A_LR0_B   3952
#define A_SIGMA_W 4016
#define A_VIEW_WT 4080    // [4][19]
#define A_VIEW_B  4156
#define A_SC      4176    // aggw_b, sigma_b
#define A_TOTAL   4180
// B section (color kernel), base in g_wt
#define GB_BASE   4608
#define B_C1WT    0       // [111][64]
#define B_C1B     7104
#define B_C2W     7168
#define B_C2B     7232
#define B_TOTAL   7236
#define GWT_TOTAL (GB_BASE + B_TOTAL)

__device__ __align__(16) float g_wt[GWT_TOTAL];

// ---------------- packed f32x2 helpers ----------------
__device__ __forceinline__ ull ffma2(ull a, ull b, ull c) {
    ull d; asm("fma.rn.f32x2 %0, %1, %2, %3;" : "=l"(d) : "l"(a), "l"(b), "l"(c));
    return d;
}
__device__ __forceinline__ ull fmul2(ull a, ull b) {
    ull d; asm("mul.rn.f32x2 %0, %1, %2;" : "=l"(d) : "l"(a), "l"(b));
    return d;
}
__device__ __forceinline__ ull fadd2(ull a, ull b) {
    ull d; asm("add.rn.f32x2 %0, %1, %2;" : "=l"(d) : "l"(a), "l"(b));
    return d;
}
__device__ __forceinline__ ull pack2(float x) {
    ull r; asm("mov.b64 %0, {%1, %1};" : "=l"(r) : "r"(__float_as_uint(x)));
    return r;
}
__device__ __forceinline__ ull pack2f(float a, float b) {
    ull r; asm("mov.b64 %0, {%1, %2};" : "=l"(r)
               : "r"(__float_as_uint(a)), "r"(__float_as_uint(b)));
    return r;
}
__device__ __forceinline__ float2 unpack2(ull v) {
    unsigned lo, hi; asm("mov.b64 {%0, %1}, %2;" : "=r"(lo), "=r"(hi) : "l"(v));
    return make_float2(__uint_as_float(lo), __uint_as_float(hi));
}
__device__ __forceinline__ ull relu2(ull v) {
    float2 f = unpack2(v);
    return pack2f(fmaxf(f.x, 0.0f), fmaxf(f.y, 0.0f));
}
__device__ __forceinline__ float halfOf(ull v, int hi) {
    float2 f = unpack2(v);
    return hi ? f.y : f.x;
}

// 32-j accumulator (16 ull)
#define ACC16(acc, xx, woff)                                                     \
    {                                                                            \
        const ulonglong2* w2 = reinterpret_cast<const ulonglong2*>(sw + (woff)); \
        _Pragma("unroll")                                                        \
        for (int q = 0; q < 8; q++) {                                            \
            ulonglong2 ww = w2[q];                                               \
            acc[2 * q]     = ffma2(ww.x, (xx), acc[2 * q]);                      \
            acc[2 * q + 1] = ffma2(ww.y, (xx), acc[2 * q + 1]);                  \
        }                                                                        \
    }
// 16-j accumulator (8 ull)
#define ACC8(acc, xx, woff)                                                      \
    {                                                                            \
        const ulonglong2* w2 = reinterpret_cast<const ulonglong2*>(sw + (woff)); \
        _Pragma("unroll")                                                        \
        for (int q = 0; q < 4; q++) {                                            \
            ulonglong2 ww = w2[q];                                               \
            acc[2 * q]     = ffma2(ww.x, (xx), acc[2 * q]);                      \
            acc[2 * q + 1] = ffma2(ww.y, (xx), acc[2 * q + 1]);                  \
        }                                                                        \
    }
#define LOADB16(acc, off)                                                        \
    {                                                                            \
        const ulonglong2* b2 = reinterpret_cast<const ulonglong2*>(sw + (off));  \
        _Pragma("unroll")                                                        \
        for (int q = 0; q < 8; q++) {                                            \
            ulonglong2 bb = b2[q];                                               \
            acc[2 * q] = bb.x; acc[2 * q + 1] = bb.y;                            \
        }                                                                        \
    }
#define LOADB8(acc, off)                                                         \
    {                                                                            \
        const ulonglong2* b2 = reinterpret_cast<const ulonglong2*>(sw + (off));  \
        _Pragma("unroll")                                                        \
        for (int q = 0; q < 4; q++) {                                            \
            ulonglong2 bb = b2[q];                                               \
            acc[2 * q] = bb.x; acc[2 * q + 1] = bb.y;                            \
        }                                                                        \
    }

// ---------------- prep: transpose weights into g_wt ----------------
__global__ void prep_kernel(const float* __restrict__ view_w, const float* __restrict__ view_b,
                            const float* __restrict__ glob_w, const float* __restrict__ glob_b,
                            const float* __restrict__ aggw_w, const float* __restrict__ aggw_b,
                            const float* __restrict__ fc_w,   const float* __restrict__ fc_b,
                            const float* __restrict__ lr0_w,  const float* __restrict__ lr0_b,
                            const float* __restrict__ sigma_w,const float* __restrict__ sigma_b,
                            const float* __restrict__ col1_w, const float* __restrict__ col1_b,
                            const float* __restrict__ col2_w, const float* __restrict__ col2_b) {
    const int t = threadIdx.x;
    const int bs = blockDim.x;
    for (int idx = t; idx < 32 * 57; idx += bs) {
        int j = idx / 57, k = idx % 57;
        g_wt[A_GLOB_WT + k * 32 + j] = glob_w[idx];
    }
    for (int idx = t; idx < 32; idx += bs) {
        g_wt[A_GLOB_B + idx] = glob_b[idx];
        g_wt[A_AGGW + idx]   = aggw_w[idx];
    }
    for (int idx = t; idx < 16 * 32; idx += bs) {
        int j = idx / 32, k = idx % 32;
        g_wt[A_FC_WT + k * 16 + j] = fc_w[idx];
    }
    for (int idx = t; idx < 16; idx += bs) g_wt[A_FC_B + idx] = fc_b[idx];
    for (int idx = t; idx < 64 * 24; idx += bs) {
        int j = idx / 24, k = idx % 24;
        g_wt[A_LR0_WT + k * 64 + j] = lr0_w[idx];
    }
    for (int idx = t; idx < 64; idx += bs) {
        g_wt[A_LR0_B + idx]   = lr0_b[idx];
        g_wt[A_SIGMA_W + idx] = sigma_w[idx];
        g_wt[GB_BASE + B_C1B + idx] = col1_b[idx];
        g_wt[GB_BASE + B_C2W + idx] = col2_w[idx];
    }
    for (int idx = t; idx < 64 * 111; idx += bs) {
        int j = idx / 111, k = idx % 111;
        g_wt[GB_BASE + B_C1WT + k * 64 + j] = col1_w[idx];
    }
    for (int idx = t; idx < 76; idx += bs) {
        int j = idx / 4, k = idx % 4;
        g_wt[A_VIEW_WT + k * 19 + j] = view_w[idx];
    }
    for (int idx = t; idx < 19; idx += bs) g_wt[A_VIEW_B + idx] = view_b[idx];
    if (t == 0) {
        g_wt[A_SC + 0] = aggw_b[0];
        g_wt[A_SC + 1] = sigma_b[0];
        g_wt[GB_BASE + B_C2B] = col2_b[0];
    }
}

// ---------------- input transpose: [rows][cols] -> [cols][rows] ----------------
__global__ void transpose_kernel(const float* __restrict__ in, float* __restrict__ outp,
                                 int rows, int cols) {
    __shared__ float tile[32][33];
    const int c0 = blockIdx.y * 32;
    const long long r0 = (long long)blockIdx.x * 32;
    const int tx = threadIdx.x, ty = threadIdx.y;
#pragma unroll
    for (int i = 0; i < 32; i += 8) {
        long long r = r0 + ty + i;
        int c = c0 + tx;
        if (r < rows && c < cols) tile[ty + i][tx] = in[r * cols + c];
    }
    __syncthreads();
#pragma unroll
    for (int i = 0; i < 32; i += 8) {
        int c = c0 + ty + i;
        long long r = r0 + tx;
        if (r < rows && c < cols) outp[(size_t)c * rows + r] = tile[tx][ty + i];
    }
}

#define TB 128
#define PTSB 256   // points per block (P=2)

// ================= Kernel A: trunk (view/glob/agg/fc/lr0/sigma) =================
__global__ void __launch_bounds__(TB, 3)
nerfA(float* __restrict__ out, int N) {
    extern __shared__ char dynsmem[];
    ull* sbuf = (ull*)dynsmem;   // gf_base spill: 16 ull x 256 pts = 32KB
    __shared__ __align__(16) float sw[A_TOTAL];

    for (int idx = threadIdx.x; idx < A_TOTAL; idx += TB) sw[idx] = g_wt[idx];
    __syncthreads();

    const int t = threadIdx.x;
    const int base = blockIdx.x * PTSB;
    const int pt0 = base + t;
    const int pt1 = base + 128 + t;
    const bool v0 = pt0 < N;
    const bool v1 = pt1 < N;
    const size_t p0 = (size_t)(v0 ? pt0 : 0);
    const size_t p1 = (size_t)(v1 ? pt1 : 0);
    const size_t sN = (size_t)N;

#define IN2(f) pack2f(g_T[(size_t)(f) * sN + p0], g_T[(size_t)(f) * sN + p1])

    // ---- dirs ----
    ull dirs[4][4];
#pragma unroll
    for (int s = 0; s < 4; s++)
#pragma unroll
        for (int c = 0; c < 4; c++) dirs[s][c] = IN2(s * 23 + 19 + c);

    // ---- Phase A: stats + gf_base -> sbuf ----
    {
        ull gfb0[16], gfb1[16];
        LOADB16(gfb0, A_GLOB_B);
#pragma unroll
        for (int q = 0; q < 16; q++) gfb1[q] = gfb0[q];

        const ull c4n = pack2(-4.0f);
        const ull third = pack2(1.0f / 3.0f);
        const ull quarter = pack2(0.25f);

#pragma unroll 2
        for (int k = 0; k < 19; k++) {
            ull sum2 = 0ull, sq2 = 0ull;
#pragma unroll
            for (int s = 0; s < 4; s++) {
                ull a = pack2(sw[A_VIEW_B + k]);
                a = ffma2(pack2(sw[A_VIEW_WT + 0 * 19 + k]), dirs[s][0], a);
                a = ffma2(pack2(sw[A_VIEW_WT + 1 * 19 + k]), dirs[s][1], a);
                a = ffma2(pack2(sw[A_VIEW_WT + 2 * 19 + k]), dirs[s][2], a);
                a = ffma2(pack2(sw[A_VIEW_WT + 3 * 19 + k]), dirs[s][3], a);
                a = relu2(a);
                ull f = fadd2(IN2(s * 23 + k), a);
                sum2 = fadd2(sum2, f);
                sq2 = ffma2(f, f, sq2);
            }
            ull m2 = fmul2(sum2, quarter);
            ull vr2 = fmul2(ffma2(m2, fmul2(m2, c4n), sq2), third);
            float2 mf = unpack2(m2), vf = unpack2(vr2);

            ull x0 = pack2(vf.x), x1 = pack2(vf.y);
            ACC16(gfb0, x0, A_GLOB_WT + (19 + k) * 32);
            ACC16(gfb1, x1, A_GLOB_WT + (19 + k) * 32);
            x0 = pack2(mf.x); x1 = pack2(mf.y);
            ACC16(gfb0, x0, A_GLOB_WT + (38 + k) * 32);
            ACC16(gfb1, x1, A_GLOB_WT + (38 + k) * 32);
        }
#pragma unroll
        for (int q = 0; q < 16; q++) {
            sbuf[q * 256 + t] = gfb0[q];
            sbuf[q * 256 + 128 + t] = gfb1[q];
        }
    }

    // ---- Phase B: per-view glob + online softmax agg ----
    ull num0[16], num1[16];
#pragma unroll
    for (int q = 0; q < 16; q++) { num0[q] = 0ull; num1[q] = 0ull; }
    float dsum0 = 0.0f, dsum1 = 0.0f, mmax0 = -1e30f, mmax1 = -1e30f;
    const float aggb = sw[A_SC + 0];

#pragma unroll
    for (int s = 0; s < 4; s++) {
        ull gf0[16], gf1[16];
#pragma unroll
        for (int q = 0; q < 16; q++) {
            gf0[q] = sbuf[q * 256 + t];
            gf1[q] = sbuf[q * 256 + 128 + t];
        }
#pragma unroll 2
        for (int k = 0; k < 19; k++) {
            ull a = pack2(sw[A_VIEW_B + k]);
            a = ffma2(pack2(sw[A_VIEW_WT + 0 * 19 + k]), dirs[s][0], a);
            a = ffma2(pack2(sw[A_VIEW_WT + 1 * 19 + k]), dirs[s][1], a);
            a = ffma2(pack2(sw[A_VIEW_WT + 2 * 19 + k]), dirs[s][2], a);
            a = ffma2(pack2(sw[A_VIEW_WT + 3 * 19 + k]), dirs[s][3], a);
            a = relu2(a);
            ull f = fadd2(IN2(s * 23 + k), a);
            float2 fi = unpack2(f);
            ull x0 = pack2(fi.x), x1 = pack2(fi.y);
            ACC16(gf0, x0, A_GLOB_WT + k * 32);
            ACC16(gf1, x1, A_GLOB_WT + k * 32);
        }
        ull la0 = 0ull, la1 = 0ull;
        {
            const ulonglong2* aw = reinterpret_cast<const ulonglong2*>(sw + A_AGGW);
#pragma unroll
            for (int q2 = 0; q2 < 8; q2++) {
                ulonglong2 a2 = aw[q2];
                gf0[2 * q2] = relu2(gf0[2 * q2]);
                gf0[2 * q2 + 1] = relu2(gf0[2 * q2 + 1]);
                gf1[2 * q2] = relu2(gf1[2 * q2]);
                gf1[2 * q2 + 1] = relu2(gf1[2 * q2 + 1]);
                la0 = ffma2(a2.x, gf0[2 * q2], la0);
                la0 = ffma2(a2.y, gf0[2 * q2 + 1], la0);
                la1 = ffma2(a2.x, gf1[2 * q2], la1);
                la1 = ffma2(a2.y, gf1[2 * q2 + 1], la1);
            }
        }
        float2 lf0 = unpack2(la0), lf1 = unpack2(la1);
        float l0 = fmaxf(lf0.x + lf0.y + aggb, 0.0f);
        float l1 = fmaxf(lf1.x + lf1.y + aggb, 0.0f);

        if (l0 > mmax0) {
            float c = __expf(mmax0 - l0); ull c2 = pack2(c);
            dsum0 *= c;
#pragma unroll
            for (int q = 0; q < 16; q++) num0[q] = fmul2(num0[q], c2);
            mmax0 = l0;
        }
        {
            float e = __expf(l0 - mmax0); dsum0 += e; ull e2 = pack2(e);
#pragma unroll
            for (int q = 0; q < 16; q++) num0[q] = ffma2(gf0[q], e2, num0[q]);
        }
        if (l1 > mmax1) {
            float c = __expf(mmax1 - l1); ull c2 = pack2(c);
            dsum1 *= c;
#pragma unroll
            for (int q = 0; q < 16; q++) num1[q] = fmul2(num1[q], c2);
            mmax1 = l1;
        }
        {
            float e = __expf(l1 - mmax1); dsum1 += e; ull e2 = pack2(e);
#pragma unroll
            for (int q = 0; q < 16; q++) num1[q] = ffma2(gf1[q], e2, num1[q]);
        }
    }

    // ---- fc: 32 -> 16, vif; write img_feat to g_VIF ----
    float vif0[24], vif1[24];
    {
        float inv0 = 1.0f / dsum0, inv1 = 1.0f / dsum1;
        ull fa0[8], fa1[8];
        LOADB8(fa0, A_FC_B);
#pragma unroll
        for (int q = 0; q < 8; q++) fa1[q] = fa0[q];
#pragma unroll 4
        for (int k = 0; k < 32; k++) {
            ull x0 = pack2(halfOf(num0[k >> 1], k & 1) * inv0);
            ull x1 = pack2(halfOf(num1[k >> 1], k & 1) * inv1);
            ACC8(fa0, x0, A_FC_WT + k * 16);
            ACC8(fa1, x1, A_FC_WT + k * 16);
        }
#pragma unroll
        for (int c = 0; c < 8; c++) {
            vif0[c] = g_voxT[(size_t)c * sN + p0];
            vif1[c] = g_voxT[(size_t)c * sN + p1];
        }
#pragma unroll
        for (int j = 0; j < 16; j++) {
            vif0[8 + j] = fmaxf(halfOf(fa0[j >> 1], j & 1), 0.0f);
            vif1[8 + j] = fmaxf(halfOf(fa1[j >> 1], j & 1), 0.0f);
            if (v0) g_VIF[(size_t)j * sN + p0] = vif0[8 + j];
            if (v1) g_VIF[(size_t)j * sN + p1] = vif1[8 + j];
        }
    }

    // ---- lr0: 24 -> 64 (two j-tiles), relu -> g_X, sigma ----
    ull siga0 = 0ull, siga1 = 0ull;
#pragma unroll
    for (int jt = 0; jt < 2; jt++) {
        const int j0 = jt * 32;
        ull xa0[16], xa1[16];
        LOADB16(xa0, A_LR0_B + j0);
#pragma unroll
        for (int q = 0; q < 16; q++) xa1[q] = xa0[q];
#pragma unroll 4
        for (int k = 0; k < 24; k++) {
            ull x0 = pack2(vif0[k]);
            ull x1 = pack2(vif1[k]);
            ACC16(xa0, x0, A_LR0_WT + k * 64 + j0);
            ACC16(xa1, x1, A_LR0_WT + k * 64 + j0);
        }
        const ulonglong2* swg = reinterpret_cast<const ulonglong2*>(sw + A_SIGMA_W + j0);
#pragma unroll
        for (int q2 = 0; q2 < 8; q2++) {
            ulonglong2 w = swg[q2];
            ull r0a = relu2(xa0[2 * q2]);
            ull r0b = relu2(xa0[2 * q2 + 1]);
            ull r1a = relu2(xa1[2 * q2]);
            ull r1b = relu2(xa1[2 * q2 + 1]);
            siga0 = ffma2(w.x, r0a, siga0);
            siga0 = ffma2(w.y, r0b, siga0);
            siga1 = ffma2(w.x, r1a, siga1);
            siga1 = ffma2(w.y, r1b, siga1);
            int j = j0 + 4 * q2;
            float2 fa = unpack2(r0a), fb = unpack2(r0b);
            if (v0) {
                g_X[(size_t)(j + 0) * sN + p0] = fa.x;
                g_X[(size_t)(j + 1) * sN + p0] = fa.y;
                g_X[(size_t)(j + 2) * sN + p0] = fb.x;
                g_X[(size_t)(j + 3) * sN + p0] = fb.y;
            }
            float2 ga = unpack2(r1a), gb = unpack2(r1b);
            if (v1) {
                g_X[(size_t)(j + 0) * sN + p1] = ga.x;
                g_X[(size_t)(j + 1) * sN + p1] = ga.y;
                g_X[(size_t)(j + 2) * sN + p1] = gb.x;
                g_X[(size_t)(j + 3) * sN + p1] = gb.y;
            }
        }
    }
    {
        float2 s0 = unpack2(siga0), s1 = unpack2(siga1);
        float l0 = s0.x + s0.y + sw[A_SC + 1];
        float l1 = s1.x + s1.y + sw[A_SC + 1];
        if (v0) out[4 * (size_t)pt0 + 3] = (l0 > 20.0f) ? l0 : log1pf(expf(l0));
        if (v1) out[4 * (size_t)pt1 + 3] = (l1 > 20.0f) ? l1 : log1pf(expf(l1));
    }
#undef IN2
}

// ================= Kernel B: color (col1/col2/softmax) =================
__global__ void __launch_bounds__(TB, 4)
nerfB(float* __restrict__ out, int N) {
    __shared__ __align__(16) float sw[B_TOTAL];
    for (int idx = threadIdx.x; idx < B_TOTAL; idx += TB)
        sw[idx] = g_wt[GB_BASE + idx];
    __syncthreads();

    const int t = threadIdx.x;
    const int base = blockIdx.x * PTSB;
    const int pt0 = base + t;
    const int pt1 = base + 128 + t;
    const bool v0 = pt0 < N;
    const bool v1 = pt1 < N;
    const size_t p0 = (size_t)(v0 ? pt0 : 0);
    const size_t p1 = (size_t)(v1 ? pt1 : 0);
    const size_t sN = (size_t)N;

    ull lacc0[4], lacc1[4];
#pragma unroll
    for (int s = 0; s < 4; s++) { lacc0[s] = 0ull; lacc1[s] = 0ull; }

#pragma unroll 1
    for (int jt = 0; jt < 4; jt++) {
        const int j0 = jt * 16;
        ull ba0[8], ba1[8];
        LOADB8(ba0, B_C1B + j0);
#pragma unroll
        for (int q = 0; q < 8; q++) ba1[q] = ba0[q];

        // x rows (k = 0..63)
#pragma unroll 2
        for (int k = 0; k < 64; k++) {
            ull x0 = pack2(__ldg(&g_X[(size_t)k * sN + p0]));
            ull x1 = pack2(__ldg(&g_X[(size_t)k * sN + p1]));
            ACC8(ba0, x0, B_C1WT + k * 64 + j0);
            ACC8(ba1, x1, B_C1WT + k * 64 + j0);
        }
        // vox rows (k = 64..71)
#pragma unroll 2
        for (int k = 0; k < 8; k++) {
            ull x0 = pack2(__ldg(&g_voxT[(size_t)k * sN + p0]));
            ull x1 = pack2(__ldg(&g_voxT[(size_t)k * sN + p1]));
            ACC8(ba0, x0, B_C1WT + (64 + k) * 64 + j0);
            ACC8(ba1, x1, B_C1WT + (64 + k) * 64 + j0);
        }
        // img_feat rows (k = 72..87)
#pragma unroll 2
        for (int k = 0; k < 16; k++) {
            ull x0 = pack2(__ldg(&g_VIF[(size_t)k * sN + p0]));
            ull x1 = pack2(__ldg(&g_VIF[(size_t)k * sN + p1]));
            ACC8(ba0, x0, B_C1WT + (72 + k) * 64 + j0);
            ACC8(ba1, x1, B_C1WT + (72 + k) * 64 + j0);
        }
        // per-view rows (k = 88..110) + col2 partial dot
#pragma unroll
        for (int s = 0; s < 4; s++) {
            ull va0[8], va1[8];
#pragma unroll
            for (int q = 0; q < 8; q++) { va0[q] = ba0[q]; va1[q] = ba1[q]; }
#pragma unroll 2
            for (int k = 0; k < 23; k++) {
                ull x0 = pack2(__ldg(&g_T[(size_t)(s * 23 + k) * sN + p0]));
                ull x1 = pack2(__ldg(&g_T[(size_t)(s * 23 + k) * sN + p1]));
                ACC8(va0, x0, B_C1WT + (88 + k) * 64 + j0);
                ACC8(va1, x1, B_C1WT + (88 + k) * 64 + j0);
            }
            const ulonglong2* cw =
                reinterpret_cast<const ulonglong2*>(sw + B_C2W + j0);
#pragma unroll
            for (int q2 = 0; q2 < 4; q2++) {
                ulonglong2 w = cw[q2];
                lacc0[s] = ffma2(w.x, relu2(va0[2 * q2]), lacc0[s]);
                lacc0[s] = ffma2(w.y, relu2(va0[2 * q2 + 1]), lacc0[s]);
                lacc1[s] = ffma2(w.x, relu2(va1[2 * q2]), lacc1[s]);
                lacc1[s] = ffma2(w.y, relu2(va1[2 * q2 + 1]), lacc1[s]);
            }
        }
    }

    // ---- color softmax + rgb output ----
    const float col2b = sw[B_C2B];
    float l0[4], l1[4];
#pragma unroll
    for (int s = 0; s < 4; s++) {
        float2 a = unpack2(lacc0[s]);
        float2 b = unpack2(lacc1[s]);
        l0[s] = fmaxf(a.x + a.y + col2b, 0.0f);
        l1[s] = fmaxf(b.x + b.y + col2b, 0.0f);
    }
    float m0 = fmaxf(fmaxf(l0[0], l0[1]), fmaxf(l0[2], l0[3]));
    float m1 = fmaxf(fmaxf(l1[0], l1[1]), fmaxf(l1[2], l1[3]));
    float cn0[3] = {0, 0, 0}, cn1[3] = {0, 0, 0}, cd0 = 0.0f, cd1 = 0.0f;
#pragma unroll
    for (int s = 0; s < 4; s++) {
        float e0 = __expf(l0[s] - m0);
        float e1 = __expf(l1[s] - m1);
        cd0 += e0; cd1 += e1;
#pragma unroll
        for (int c = 0; c < 3; c++) {
            cn0[c] += __ldg(&g_T[(size_t)(s * 23 + 16 + c) * sN + p0]) * e0;
            cn1[c] += __ldg(&g_T[(size_t)(s * 23 + 16 + c) * sN + p1]) * e1;
        }
    }
    if (v0) {
        float inv = 1.0f / cd0;
        out[4 * (size_t)pt0 + 0] = cn0[0] * inv;
        out[4 * (size_t)pt0 + 1] = cn0[1] * inv;
        out[4 * (size_t)pt0 + 2] = cn0[2] * inv;
    }
    if (v1) {
        float inv = 1.0f / cd1;
        out[4 * (size_t)pt1 + 0] = cn1[0] * inv;
        out[4 * (size_t)pt1 + 1] = cn1[1] * inv;
        out[4 * (size_t)pt1 + 2] = cn1[2] * inv;
    }
}

extern "C" void kernel_launch(void* const* d_in, const int* in_sizes, int n_in,
                              void* d_out, int out_size) {
    const float* vox     = (const float*)d_in[0];
    const float* ifrd    = (const float*)d_in[1];
    const float* view_w  = (const float*)d_in[2];
    const float* view_b  = (const float*)d_in[3];
    const float* glob_w  = (const float*)d_in[4];
    const float* glob_b  = (const float*)d_in[5];
    const float* aggw_w  = (const float*)d_in[6];
    const float* aggw_b  = (const float*)d_in[7];
    const float* fc_w    = (const float*)d_in[8];
    const float* fc_b    = (const float*)d_in[9];
    const float* lr0_w   = (const float*)d_in[10];
    const float* lr0_b   = (const float*)d_in[11];
    const float* sigma_w = (const float*)d_in[12];
    const float* sigma_b = (const float*)d_in[13];
    const float* col1_w  = (const float*)d_in[14];
    const float* col1_b  = (const float*)d_in[15];
    const float* col2_w  = (const float*)d_in[16];
    const float* col2_b  = (const float*)d_in[17];
    float* out = (float*)d_out;

    int N = in_sizes[0] / 8;
    if (N > NMAX) N = NMAX;

    // Opt-in: static (16.7KB) + dynamic (32KB) smem exceeds the 48KB default.
    cudaFuncSetAttribute(nerfA, cudaFuncAttributeMaxDynamicSharedMemorySize, 33000);

    float* tptr = nullptr;
    float* vptr = nullptr;
    cudaGetSymbolAddress((void**)&tptr, g_T);
    cudaGetSymbolAddress((void**)&vptr, g_voxT);

    prep_kernel<<<1, 256>>>(view_w, view_b, glob_w, glob_b, aggw_w, aggw_b,
                            fc_w, fc_b, lr0_w, lr0_b, sigma_w, sigma_b,
                            col1_w, col1_b, col2_w, col2_b);

    dim3 tb(32, 8);
    dim3 tg1((N + 31) / 32, (92 + 31) / 32);
    transpose_kernel<<<tg1, tb>>>(ifrd, tptr, N, 92);
    dim3 tg2((N + 31) / 32, 1);
    transpose_kernel<<<tg2, tb>>>(vox, vptr, N, 8);

    int blocks = (N + PTSB - 1) / PTSB;
    nerfA<<<blocks, TB, 32768>>>(out, N);
    nerfB<<<blocks, TB>>>(out, N);
}

// round 14
// speedup vs baseline: 1.7885x; 1.7885x over previous
#include <cuda_runtime.h>
#include <math.h>

typedef unsigned long long ull;

#define NMAX 524288

// ---------------- device-global scratch ----------------
__device__ __align__(16) float g_T[92 * NMAX];     // ifrd transposed: [feat][pt]

// Transposed weight layout (floats). wt[k*J + j], j contiguous.
#define OFF_GLOB_WT 0       // [57][32]
#define OFF_GLOB_B  1824    // [32]
#define OFF_AGGW    1856    // [32]
#define OFF_FC_WT   1888    // [32][16]
#define OFF_FC_B    2400    // [16]
#define OFF_LR0_WT  2416    // [24][64]
#define OFF_LR0_B   3952    // [64]
#define OFF_SIGMA_W 4016    // [64]
#define OFF_COL1_WT 4080    // [111][64]
#define OFF_COL1_B  11184   // [64]
#define OFF_COL2_W  11248   // [64]
#define OFF_VIEW_WT 11312   // [4][19]
#define OFF_VIEW_B  11388   // [19]
#define OFF_SC      11407   // aggw_b, sigma_b, col2_b
#define WT_TOTAL    11410

__device__ __align__(16) float g_wt[WT_TOTAL + 2];

// ---------------- packed f32x2 helpers ----------------
__device__ __forceinline__ ull ffma2(ull a, ull b, ull c) {
    ull d; asm("fma.rn.f32x2 %0, %1, %2, %3;" : "=l"(d) : "l"(a), "l"(b), "l"(c));
    return d;
}
__device__ __forceinline__ ull fmul2(ull a, ull b) {
    ull d; asm("mul.rn.f32x2 %0, %1, %2;" : "=l"(d) : "l"(a), "l"(b));
    return d;
}
__device__ __forceinline__ ull fadd2(ull a, ull b) {
    ull d; asm("add.rn.f32x2 %0, %1, %2;" : "=l"(d) : "l"(a), "l"(b));
    return d;
}
__device__ __forceinline__ ull pack2(float x) {
    ull r; asm("mov.b64 %0, {%1, %1};" : "=l"(r) : "r"(__float_as_uint(x)));
    return r;
}
__device__ __forceinline__ ull pack2f(float a, float b) {
    ull r; asm("mov.b64 %0, {%1, %2};" : "=l"(r)
               : "r"(__float_as_uint(a)), "r"(__float_as_uint(b)));
    return r;
}
__device__ __forceinline__ float2 unpack2(ull v) {
    unsigned lo, hi; asm("mov.b64 {%0, %1}, %2;" : "=r"(lo), "=r"(hi) : "l"(v));
    return make_float2(__uint_as_float(lo), __uint_as_float(hi));
}
__device__ __forceinline__ ull relu2(ull v) {
    float2 f = unpack2(v);
    return pack2f(fmaxf(f.x, 0.0f), fmaxf(f.y, 0.0f));
}
__device__ __forceinline__ float halfOf(ull v, int hi) {
    float2 f = unpack2(v);
    return hi ? f.y : f.x;
}

// acc is ull[16] (32 j outputs, j-packed). xx = pack2(scalar).
#define ACC16(acc, xx, woff)                                                     \
    {                                                                            \
        const ulonglong2* w2 = reinterpret_cast<const ulonglong2*>(sw + (woff)); \
        _Pragma("unroll")                                                        \
        for (int q = 0; q < 8; q++) {                                            \
            ulonglong2 ww = w2[q];                                               \
            acc[2 * q]     = ffma2(ww.x, (xx), acc[2 * q]);                      \
            acc[2 * q + 1] = ffma2(ww.y, (xx), acc[2 * q + 1]);                  \
        }                                                                        \
    }
#define ACC8(acc, xx, woff)                                                      \
    {                                                                            \
        const ulonglong2* w2 = reinterpret_cast<const ulonglong2*>(sw + (woff)); \
        _Pragma("unroll")                                                        \
        for (int q = 0; q < 4; q++) {                                            \
            ulonglong2 ww = w2[q];                                               \
            acc[2 * q]     = ffma2(ww.x, (xx), acc[2 * q]);                      \
            acc[2 * q + 1] = ffma2(ww.y, (xx), acc[2 * q + 1]);                  \
        }                                                                        \
    }
#define LOADB16(acc, off)                                                        \
    {                                                                            \
        const ulonglong2* b2 = reinterpret_cast<const ulonglong2*>(sw + (off));  \
        _Pragma("unroll")                                                        \
        for (int q = 0; q < 8; q++) {                                            \
            ulonglong2 bb = b2[q];                                               \
            acc[2 * q] = bb.x; acc[2 * q + 1] = bb.y;                            \
        }                                                                        \
    }
#define LOADB8(acc, off)                                                         \
    {                                                                            \
        const ulonglong2* b2 = reinterpret_cast<const ulonglong2*>(sw + (off));  \
        _Pragma("unroll")                                                        \
        for (int q = 0; q < 4; q++) {                                            \
            ulonglong2 bb = b2[q];                                               \
            acc[2 * q] = bb.x; acc[2 * q + 1] = bb.y;                            \
        }                                                                        \
    }

// ---------------- prep: transpose weights into g_wt ----------------
__global__ void prep_kernel(const float* __restrict__ view_w, const float* __restrict__ view_b,
                            const float* __restrict__ glob_w, const float* __restrict__ glob_b,
                            const float* __restrict__ aggw_w, const float* __restrict__ aggw_b,
                            const float* __restrict__ fc_w,   const float* __restrict__ fc_b,
                            const float* __restrict__ lr0_w,  const float* __restrict__ lr0_b,
                            const float* __restrict__ sigma_w,const float* __restrict__ sigma_b,
                            const float* __restrict__ col1_w, const float* __restrict__ col1_b,
                            const float* __restrict__ col2_w, const float* __restrict__ col2_b) {
    const int t = threadIdx.x;
    const int bs = blockDim.x;
    for (int idx = t; idx < 32 * 57; idx += bs) {
        int j = idx / 57, k = idx % 57;
        g_wt[OFF_GLOB_WT + k * 32 + j] = glob_w[idx];
    }
    for (int idx = t; idx < 32; idx += bs) {
        g_wt[OFF_GLOB_B + idx] = glob_b[idx];
        g_wt[OFF_AGGW + idx]   = aggw_w[idx];
    }
    for (int idx = t; idx < 16 * 32; idx += bs) {
        int j = idx / 32, k = idx % 32;
        g_wt[OFF_FC_WT + k * 16 + j] = fc_w[idx];
    }
    for (int idx = t; idx < 16; idx += bs) g_wt[OFF_FC_B + idx] = fc_b[idx];
    for (int idx = t; idx < 64 * 24; idx += bs) {
        int j = idx / 24, k = idx % 24;
        g_wt[OFF_LR0_WT + k * 64 + j] = lr0_w[idx];
    }
    for (int idx = t; idx < 64; idx += bs) {
        g_wt[OFF_LR0_B + idx]   = lr0_b[idx];
        g_wt[OFF_SIGMA_W + idx] = sigma_w[idx];
        g_wt[OFF_COL1_B + idx]  = col1_b[idx];
        g_wt[OFF_COL2_W + idx]  = col2_w[idx];
    }
    for (int idx = t; idx < 64 * 111; idx += bs) {
        int j = idx / 111, k = idx % 111;
        g_wt[OFF_COL1_WT + k * 64 + j] = col1_w[idx];
    }
    for (int idx = t; idx < 76; idx += bs) {
        int j = idx / 4, k = idx % 4;
        g_wt[OFF_VIEW_WT + k * 19 + j] = view_w[idx];
    }
    for (int idx = t; idx < 19; idx += bs) g_wt[OFF_VIEW_B + idx] = view_b[idx];
    if (t == 0) {
        g_wt[OFF_SC + 0] = aggw_b[0];
        g_wt[OFF_SC + 1] = sigma_b[0];
        g_wt[OFF_SC + 2] = col2_b[0];
    }
}

// ---------------- input transpose: [rows][cols] -> [cols][rows] ----------------
__global__ void transpose_kernel(const float* __restrict__ in, float* __restrict__ outp,
                                 int rows, int cols) {
    __shared__ float tile[32][33];
    const int c0 = blockIdx.y * 32;
    const long long r0 = (long long)blockIdx.x * 32;
    const int tx = threadIdx.x, ty = threadIdx.y;
#pragma unroll
    for (int i = 0; i < 32; i += 8) {
        long long r = r0 + ty + i;
        int c = c0 + tx;
        if (r < rows && c < cols) tile[ty + i][tx] = in[r * cols + c];
    }
    __syncthreads();
#pragma unroll
    for (int i = 0; i < 32; i += 8) {
        int c = c0 + ty + i;
        long long r = r0 + tx;
        if (r < rows && c < cols) outp[(size_t)c * rows + r] = tile[tx][ty + i];
    }
}

// ---------------- main kernel ----------------
#define TB 128
#define PTSB 256   // points per block (P=2, adjacent pairs)

__global__ void __launch_bounds__(TB)
nerf_main(const float* __restrict__ vox, float* __restrict__ out, int N) {
    extern __shared__ char dynsmem[];
    ull* sbuf = (ull*)dynsmem;                 // 32*256 ull = 64KB thread-private scratch
    __shared__ __align__(16) float sw[WT_TOTAL + 2];

    for (int idx = threadIdx.x; idx < WT_TOTAL; idx += TB) sw[idx] = g_wt[idx];
    __syncthreads();

    const int t = threadIdx.x;
    const int base = blockIdx.x * PTSB;
    const int pt0 = base + 2 * t;       // even; pt1 = pt0 + 1
    const int pt1 = pt0 + 1;
    const bool vld = pt0 < N;           // N even -> pt1 < N iff pt0 < N
    const size_t pb = (size_t)(vld ? pt0 : 0);   // 8B-aligned pair base
    const size_t sN = (size_t)N;

    // One aligned 8-byte load fetches the (pt0, pt1) pair, pre-packed for f32x2.
#define IN2(f) __ldg(reinterpret_cast<const ull*>(&g_T[(size_t)(f) * sN + pb]))

    // ============ Phase A: dirs, stats, gf_base (spilled to sbuf) ============
    ull dirs[4][4];
#pragma unroll
    for (int s = 0; s < 4; s++)
#pragma unroll
        for (int c = 0; c < 4; c++) dirs[s][c] = IN2(s * 23 + 19 + c);

    {
        ull gfb0[16], gfb1[16];
        LOADB16(gfb0, OFF_GLOB_B);
#pragma unroll
        for (int q = 0; q < 16; q++) gfb1[q] = gfb0[q];

        const ull c4n = pack2(-4.0f);
        const ull third = pack2(1.0f / 3.0f);
        const ull quarter = pack2(0.25f);

#pragma unroll 2
        for (int k = 0; k < 19; k++) {
            ull sum2 = 0ull, sq2 = 0ull;
#pragma unroll
            for (int s = 0; s < 4; s++) {
                ull a = pack2(sw[OFF_VIEW_B + k]);
                a = ffma2(pack2(sw[OFF_VIEW_WT + 0 * 19 + k]), dirs[s][0], a);
                a = ffma2(pack2(sw[OFF_VIEW_WT + 1 * 19 + k]), dirs[s][1], a);
                a = ffma2(pack2(sw[OFF_VIEW_WT + 2 * 19 + k]), dirs[s][2], a);
                a = ffma2(pack2(sw[OFF_VIEW_WT + 3 * 19 + k]), dirs[s][3], a);
                a = relu2(a);
                ull f = fadd2(IN2(s * 23 + k), a);
                sum2 = fadd2(sum2, f);
                sq2 = ffma2(f, f, sq2);
            }
            ull m2 = fmul2(sum2, quarter);
            ull vr2 = fmul2(ffma2(m2, fmul2(m2, c4n), sq2), third);
            float2 mf = unpack2(m2), vf = unpack2(vr2);

            ull x0 = pack2(vf.x), x1 = pack2(vf.y);
            ACC16(gfb0, x0, OFF_GLOB_WT + (19 + k) * 32);
            ACC16(gfb1, x1, OFF_GLOB_WT + (19 + k) * 32);
            x0 = pack2(mf.x); x1 = pack2(mf.y);
            ACC16(gfb0, x0, OFF_GLOB_WT + (38 + k) * 32);
            ACC16(gfb1, x1, OFF_GLOB_WT + (38 + k) * 32);
        }
#pragma unroll
        for (int q = 0; q < 16; q++) {
            sbuf[q * 256 + t] = gfb0[q];
            sbuf[q * 256 + 128 + t] = gfb1[q];
        }
    }

    // ============ Phase B: per-view glob + online softmax agg ============
    ull num0[16], num1[16];
#pragma unroll
    for (int q = 0; q < 16; q++) { num0[q] = 0ull; num1[q] = 0ull; }
    float dsum0 = 0.0f, dsum1 = 0.0f, mmax0 = -1e30f, mmax1 = -1e30f;
    const float aggb = sw[OFF_SC + 0];

#pragma unroll
    for (int s = 0; s < 4; s++) {
        ull gf0[16], gf1[16];
#pragma unroll
        for (int q = 0; q < 16; q++) {
            gf0[q] = sbuf[q * 256 + t];
            gf1[q] = sbuf[q * 256 + 128 + t];
        }
#pragma unroll 2
        for (int k = 0; k < 19; k++) {
            ull a = pack2(sw[OFF_VIEW_B + k]);
            a = ffma2(pack2(sw[OFF_VIEW_WT + 0 * 19 + k]), dirs[s][0], a);
            a = ffma2(pack2(sw[OFF_VIEW_WT + 1 * 19 + k]), dirs[s][1], a);
            a = ffma2(pack2(sw[OFF_VIEW_WT + 2 * 19 + k]), dirs[s][2], a);
            a = ffma2(pack2(sw[OFF_VIEW_WT + 3 * 19 + k]), dirs[s][3], a);
            a = relu2(a);
            ull f = fadd2(IN2(s * 23 + k), a);
            float2 fi = unpack2(f);
            ull x0 = pack2(fi.x), x1 = pack2(fi.y);
            ACC16(gf0, x0, OFF_GLOB_WT + k * 32);
            ACC16(gf1, x1, OFF_GLOB_WT + k * 32);
        }
        ull la0 = 0ull, la1 = 0ull;
        {
            const ulonglong2* aw = reinterpret_cast<const ulonglong2*>(sw + OFF_AGGW);
#pragma unroll
            for (int q2 = 0; q2 < 8; q2++) {
                ulonglong2 a2 = aw[q2];
                gf0[2 * q2] = relu2(gf0[2 * q2]);
                gf0[2 * q2 + 1] = relu2(gf0[2 * q2 + 1]);
                gf1[2 * q2] = relu2(gf1[2 * q2]);
                gf1[2 * q2 + 1] = relu2(gf1[2 * q2 + 1]);
                la0 = ffma2(a2.x, gf0[2 * q2], la0);
                la0 = ffma2(a2.y, gf0[2 * q2 + 1], la0);
                la1 = ffma2(a2.x, gf1[2 * q2], la1);
                la1 = ffma2(a2.y, gf1[2 * q2 + 1], la1);
            }
        }
        float2 lf0 = unpack2(la0), lf1 = unpack2(la1);
        float l0 = fmaxf(lf0.x + lf0.y + aggb, 0.0f);
        float l1 = fmaxf(lf1.x + lf1.y + aggb, 0.0f);

        if (l0 > mmax0) {
            float c = __expf(mmax0 - l0); ull c2 = pack2(c);
            dsum0 *= c;
#pragma unroll
            for (int q = 0; q < 16; q++) num0[q] = fmul2(num0[q], c2);
            mmax0 = l0;
        }
        {
            float e = __expf(l0 - mmax0); dsum0 += e; ull e2 = pack2(e);
#pragma unroll
            for (int q = 0; q < 16; q++) num0[q] = ffma2(gf0[q], e2, num0[q]);
        }
        if (l1 > mmax1) {
            float c = __expf(mmax1 - l1); ull c2 = pack2(c);
            dsum1 *= c;
#pragma unroll
            for (int q = 0; q < 16; q++) num1[q] = fmul2(num1[q], c2);
            mmax1 = l1;
        }
        {
            float e = __expf(l1 - mmax1); dsum1 += e; ull e2 = pack2(e);
#pragma unroll
            for (int q = 0; q < 16; q++) num1[q] = ffma2(gf1[q], e2, num1[q]);
        }
    }

    // ============ fc: 32 -> 16, build vif[2][24] ============
    float vif0[24], vif1[24];
    {
        float inv0 = 1.0f / dsum0, inv1 = 1.0f / dsum1;
        ull fa0[8], fa1[8];
        LOADB8(fa0, OFF_FC_B);
#pragma unroll
        for (int q = 0; q < 8; q++) fa1[q] = fa0[q];
#pragma unroll 4
        for (int k = 0; k < 32; k++) {
            ull x0 = pack2(halfOf(num0[k >> 1], k & 1) * inv0);
            ull x1 = pack2(halfOf(num1[k >> 1], k & 1) * inv1);
            ACC8(fa0, x0, OFF_FC_WT + k * 16);
            ACC8(fa1, x1, OFF_FC_WT + k * 16);
        }
        // vox AoS: pts pt0/pt1 adjacent -> 4 coalesced float4 loads
        const float4* vp4 = reinterpret_cast<const float4*>(vox + pb * 8);
        float4 va = __ldg(vp4),     vb = __ldg(vp4 + 1);
        float4 vc = __ldg(vp4 + 2), vd = __ldg(vp4 + 3);
        vif0[0] = va.x; vif0[1] = va.y; vif0[2] = va.z; vif0[3] = va.w;
        vif0[4] = vb.x; vif0[5] = vb.y; vif0[6] = vb.z; vif0[7] = vb.w;
        vif1[0] = vc.x; vif1[1] = vc.y; vif1[2] = vc.z; vif1[3] = vc.w;
        vif1[4] = vd.x; vif1[5] = vd.y; vif1[6] = vd.z; vif1[7] = vd.w;
#pragma unroll
        for (int j = 0; j < 16; j++) {
            vif0[8 + j] = fmaxf(halfOf(fa0[j >> 1], j & 1), 0.0f);
            vif1[8 + j] = fmaxf(halfOf(fa1[j >> 1], j & 1), 0.0f);
        }
    }

    // ============ lr0: 24 -> 64 (two j-tiles), relu, sigma partial, x->sbuf ====
    ull siga0 = 0ull, siga1 = 0ull;
#pragma unroll
    for (int jt = 0; jt < 2; jt++) {
        const int j0 = jt * 32;
        ull xa0[16], xa1[16];
        LOADB16(xa0, OFF_LR0_B + j0);
#pragma unroll
        for (int q = 0; q < 16; q++) xa1[q] = xa0[q];
#pragma unroll 4
        for (int k = 0; k < 24; k++) {
            ull x0 = pack2(vif0[k]);
            ull x1 = pack2(vif1[k]);
            ACC16(xa0, x0, OFF_LR0_WT + k * 64 + j0);
            ACC16(xa1, x1, OFF_LR0_WT + k * 64 + j0);
        }
        const ulonglong2* swg = reinterpret_cast<const ulonglong2*>(sw + OFF_SIGMA_W + j0);
#pragma unroll
        for (int q2 = 0; q2 < 8; q2++) {
            ulonglong2 w = swg[q2];
            ull r0a = relu2(xa0[2 * q2]);
            ull r0b = relu2(xa0[2 * q2 + 1]);
            ull r1a = relu2(xa1[2 * q2]);
            ull r1b = relu2(xa1[2 * q2 + 1]);
            siga0 = ffma2(w.x, r0a, siga0);
            siga0 = ffma2(w.y, r0b, siga0);
            siga1 = ffma2(w.x, r1a, siga1);
            siga1 = ffma2(w.y, r1b, siga1);
            sbuf[(jt * 16 + 2 * q2) * 256 + t] = r0a;
            sbuf[(jt * 16 + 2 * q2 + 1) * 256 + t] = r0b;
            sbuf[(jt * 16 + 2 * q2) * 256 + 128 + t] = r1a;
            sbuf[(jt * 16 + 2 * q2 + 1) * 256 + 128 + t] = r1b;
        }
    }
    float sig0, sig1;
    {
        float2 s0 = unpack2(siga0), s1 = unpack2(siga1);
        float l0 = s0.x + s0.y + sw[OFF_SC + 1];
        float l1 = s1.x + s1.y + sw[OFF_SC + 1];
        sig0 = (l0 > 20.0f) ? l0 : log1pf(expf(l0));
        sig1 = (l1 > 20.0f) ? l1 : log1pf(expf(l1));
    }

    // ============ col1 (j-tiled) + col2 partial logits ============
    ull lacc0[4], lacc1[4];
#pragma unroll
    for (int s = 0; s < 4; s++) { lacc0[s] = 0ull; lacc1[s] = 0ull; }
    const float* sbf = (const float*)sbuf;

#pragma unroll
    for (int jt = 0; jt < 2; jt++) {
        const int j0 = jt * 32;
        ull ba0[16], ba1[16];
        LOADB16(ba0, OFF_COL1_B + j0);
#pragma unroll
        for (int q = 0; q < 16; q++) ba1[q] = ba0[q];
#pragma unroll 2
        for (int k = 0; k < 64; k++) {
            float xv0 = sbf[(k >> 1) * 512 + t * 2 + (k & 1)];
            float xv1 = sbf[(k >> 1) * 512 + (128 + t) * 2 + (k & 1)];
            ull x0 = pack2(xv0);
            ull x1 = pack2(xv1);
            ACC16(ba0, x0, OFF_COL1_WT + k * 64 + j0);
            ACC16(ba1, x1, OFF_COL1_WT + k * 64 + j0);
        }
#pragma unroll 2
        for (int k = 0; k < 24; k++) {
            ull x0 = pack2(vif0[k]);
            ull x1 = pack2(vif1[k]);
            ACC16(ba0, x0, OFF_COL1_WT + (64 + k) * 64 + j0);
            ACC16(ba1, x1, OFF_COL1_WT + (64 + k) * 64 + j0);
        }
#pragma unroll
        for (int s = 0; s < 4; s++) {
            ull va0[16], va1[16];
#pragma unroll
            for (int q = 0; q < 16; q++) { va0[q] = ba0[q]; va1[q] = ba1[q]; }
#pragma unroll 2
            for (int k = 0; k < 23; k++) {
                ull f2 = IN2(s * 23 + k);
                float2 fv = unpack2(f2);
                ull x0 = pack2(fv.x);
                ull x1 = pack2(fv.y);
                ACC16(va0, x0, OFF_COL1_WT + (88 + k) * 64 + j0);
                ACC16(va1, x1, OFF_COL1_WT + (88 + k) * 64 + j0);
            }
            const ulonglong2* cw =
                reinterpret_cast<const ulonglong2*>(sw + OFF_COL2_W + j0);
#pragma unroll
            for (int q2 = 0; q2 < 8; q2++) {
                ulonglong2 w = cw[q2];
                lacc0[s] = ffma2(w.x, relu2(va0[2 * q2]), lacc0[s]);
                lacc0[s] = ffma2(w.y, relu2(va0[2 * q2 + 1]), lacc0[s]);
                lacc1[s] = ffma2(w.x, relu2(va1[2 * q2]), lacc1[s]);
                lacc1[s] = ffma2(w.y, relu2(va1[2 * q2 + 1]), lacc1[s]);
            }
        }
    }

    // ============ color softmax + output ============
    const float col2b = sw[OFF_SC + 2];
    float l0[4], l1[4];
#pragma unroll
    for (int s = 0; s < 4; s++) {
        float2 a = unpack2(lacc0[s]);
        float2 b = unpack2(lacc1[s]);
        l0[s] = fmaxf(a.x + a.y + col2b, 0.0f);
        l1[s] = fmaxf(b.x + b.y + col2b, 0.0f);
    }
    float m0 = fmaxf(fmaxf(l0[0], l0[1]), fmaxf(l0[2], l0[3]));
    float m1 = fmaxf(fmaxf(l1[0], l1[1]), fmaxf(l1[2], l1[3]));
    float cn0[3] = {0, 0, 0}, cn1[3] = {0, 0, 0}, cd0 = 0.0f, cd1 = 0.0f;
#pragma unroll
    for (int s = 0; s < 4; s++) {
        float e0 = __expf(l0[s] - m0);
        float e1 = __expf(l1[s] - m1);
        cd0 += e0; cd1 += e1;
#pragma unroll
        for (int c = 0; c < 3; c++) {
            float2 rgb = unpack2(IN2(s * 23 + 16 + c));
            cn0[c] += rgb.x * e0;
            cn1[c] += rgb.y * e1;
        }
    }
    if (vld) {
        float inv0 = 1.0f / cd0;
        float inv1 = 1.0f / cd1;
        float4 o0 = make_float4(cn0[0] * inv0, cn0[1] * inv0, cn0[2] * inv0, sig0);
        float4 o1 = make_float4(cn1[0] * inv1, cn1[1] * inv1, cn1[2] * inv1, sig1);
        reinterpret_cast<float4*>(out)[pt0] = o0;
        reinterpret_cast<float4*>(out)[pt1] = o1;
    }
#undef IN2
}

extern "C" void kernel_launch(void* const* d_in, const int* in_sizes, int n_in,
                              void* d_out, int out_size) {
    const float* vox     = (const float*)d_in[0];
    const float* ifrd    = (const float*)d_in[1];
    const float* view_w  = (const float*)d_in[2];
    const float* view_b  = (const float*)d_in[3];
    const float* glob_w  = (const float*)d_in[4];
    const float* glob_b  = (const float*)d_in[5];
    const float* aggw_w  = (const float*)d_in[6];
    const float* aggw_b  = (const float*)d_in[7];
    const float* fc_w    = (const float*)d_in[8];
    const float* fc_b    = (const float*)d_in[9];
    const float* lr0_w   = (const float*)d_in[10];
    const float* lr0_b   = (const float*)d_in[11];
    const float* sigma_w = (const float*)d_in[12];
    const float* sigma_b = (const float*)d_in[13];
    const float* col1_w  = (const float*)d_in[14];
    const float* col1_b  = (const float*)d_in[15];
    const float* col2_w  = (const float*)d_in[16];
    const float* col2_b  = (const float*)d_in[17];
    float* out = (float*)d_out;

    int N = in_sizes[0] / 8;
    if (N > NMAX) N = NMAX;

    cudaFuncSetAttribute(nerf_main, cudaFuncAttributeMaxDynamicSharedMemorySize, 65536);

    float* tptr = nullptr;
    cudaGetSymbolAddress((void**)&tptr, g_T);

    prep_kernel<<<1, 256>>>(view_w, view_b, glob_w, glob_b, aggw_w, aggw_b,
                            fc_w, fc_b, lr0_w, lr0_b, sigma_w, sigma_b,
                            col1_w, col1_b, col2_w, col2_b);

    dim3 tb(32, 8);
    dim3 tg1((N + 31) / 32, (92 + 31) / 32);
    transpose_kernel<<<tg1, tb>>>(ifrd, tptr, N, 92);

    int blocks = (N + PTSB - 1) / PTSB;
    nerf_main<<<blocks, TB, 65536>>>(vox, out, N);
}

// round 15
// speedup vs baseline: 1.9940x; 1.1149x over previous
#include <cuda_runtime.h>
#include <cuda_fp16.h>
#include <math.h>

typedef unsigned long long ull;

#define NMAX 524288

// ---------------- device-global scratch ----------------
__device__ __align__(16) float g_T[92 * NMAX];     // ifrd transposed: [feat][pt]

// ---------------- weight layout in g_wt ----------------
// Stage-1 section (phases A/B/fc/lr0/sigma), offsets inside smem overlay:
#define A_GLOB_WT 0       // [57][32]
#define A_GLOB_B  1824
#define A_AGGW    1856
#define A_FC_WT   1888    // [32][16]
#define A_FC_B    2400
#define A_LR0_WT  2416    // [24][64]
#define A_LR0_B   3952
#define A_SIGMA_W 4016
#define A_VIEW_WT 4080    // [4][19]
#define A_VIEW_B  4156
#define A_SC      4176    // aggw_b, sigma_b
#define A_TOTAL   4180
// Stage-2 section (col1/col2), offsets inside smem overlay:
#define B_C1WT    0       // [111][64]
#define B_C1B     7104
#define B_C2W     7168
#define B_C2B     7232
#define B_TOTAL   7236
// g_wt placement: stage1 at 0, stage2 at GB_BASE
#define GB_BASE   4608
#define GWT_TOTAL (GB_BASE + B_TOTAL)

__device__ __align__(16) float g_wt[GWT_TOTAL];

// ---------------- packed f32x2 helpers ----------------
__device__ __forceinline__ ull ffma2(ull a, ull b, ull c) {
    ull d; asm("fma.rn.f32x2 %0, %1, %2, %3;" : "=l"(d) : "l"(a), "l"(b), "l"(c));
    return d;
}
__device__ __forceinline__ ull fmul2(ull a, ull b) {
    ull d; asm("mul.rn.f32x2 %0, %1, %2;" : "=l"(d) : "l"(a), "l"(b));
    return d;
}
__device__ __forceinline__ ull fadd2(ull a, ull b) {
    ull d; asm("add.rn.f32x2 %0, %1, %2;" : "=l"(d) : "l"(a), "l"(b));
    return d;
}
__device__ __forceinline__ ull pack2(float x) {
    ull r; asm("mov.b64 %0, {%1, %1};" : "=l"(r) : "r"(__float_as_uint(x)));
    return r;
}
__device__ __forceinline__ ull pack2f(float a, float b) {
    ull r; asm("mov.b64 %0, {%1, %2};" : "=l"(r)
               : "r"(__float_as_uint(a)), "r"(__float_as_uint(b)));
    return r;
}
__device__ __forceinline__ float2 unpack2(ull v) {
    unsigned lo, hi; asm("mov.b64 {%0, %1}, %2;" : "=r"(lo), "=r"(hi) : "l"(v));
    return make_float2(__uint_as_float(lo), __uint_as_float(hi));
}
__device__ __forceinline__ ull relu2(ull v) {
    float2 f = unpack2(v);
    return pack2f(fmaxf(f.x, 0.0f), fmaxf(f.y, 0.0f));
}
__device__ __forceinline__ float halfOf(ull v, int hi) {
    float2 f = unpack2(v);
    return hi ? f.y : f.x;
}

// acc is ull[16] (32 j outputs, j-packed). xx = pack2(scalar).
#define ACC16(acc, xx, woff)                                                     \
    {                                                                            \
        const ulonglong2* w2 = reinterpret_cast<const ulonglong2*>(sw + (woff)); \
        _Pragma("unroll")                                                        \
        for (int q = 0; q < 8; q++) {                                            \
            ulonglong2 ww = w2[q];                                               \
            acc[2 * q]     = ffma2(ww.x, (xx), acc[2 * q]);                      \
            acc[2 * q + 1] = ffma2(ww.y, (xx), acc[2 * q + 1]);                  \
        }                                                                        \
    }
// 16-j accumulator (8 ull)
#define ACC8(acc, xx, woff)                                                      \
    {                                                                            \
        const ulonglong2* w2 = reinterpret_cast<const ulonglong2*>(sw + (woff)); \
        _Pragma("unroll")                                                        \
        for (int q = 0; q < 4; q++) {                                            \
            ulonglong2 ww = w2[q];                                               \
            acc[2 * q]     = ffma2(ww.x, (xx), acc[2 * q]);                      \
            acc[2 * q + 1] = ffma2(ww.y, (xx), acc[2 * q + 1]);                  \
        }                                                                        \
    }
#define LOADB16(acc, off)                                                        \
    {                                                                            \
        const ulonglong2* b2 = reinterpret_cast<const ulonglong2*>(sw + (off));  \
        _Pragma("unroll")                                                        \
        for (int q = 0; q < 8; q++) {                                            \
            ulonglong2 bb = b2[q];                                               \
            acc[2 * q] = bb.x; acc[2 * q + 1] = bb.y;                            \
        }                                                                        \
    }
#define LOADB8(acc, off)                                                         \
    {                                                                            \
        const ulonglong2* b2 = reinterpret_cast<const ulonglong2*>(sw + (off));  \
        _Pragma("unroll")                                                        \
        for (int q = 0; q < 4; q++) {                                            \
            ulonglong2 bb = b2[q];                                               \
            acc[2 * q] = bb.x; acc[2 * q + 1] = bb.y;                            \
        }                                                                        \
    }

// ---------------- prep: transpose weights into g_wt ----------------
__global__ void prep_kernel(const float* __restrict__ view_w, const float* __restrict__ view_b,
                            const float* __restrict__ glob_w, const float* __restrict__ glob_b,
                            const float* __restrict__ aggw_w, const float* __restrict__ aggw_b,
                            const float* __restrict__ fc_w,   const float* __restrict__ fc_b,
                            const float* __restrict__ lr0_w,  const float* __restrict__ lr0_b,
                            const float* __restrict__ sigma_w,const float* __restrict__ sigma_b,
                            const float* __restrict__ col1_w, const float* __restrict__ col1_b,
                            const float* __restrict__ col2_w, const float* __restrict__ col2_b) {
    const int t = threadIdx.x;
    const int bs = blockDim.x;
    for (int idx = t; idx < 32 * 57; idx += bs) {
        int j = idx / 57, k = idx % 57;
        g_wt[A_GLOB_WT + k * 32 + j] = glob_w[idx];
    }
    for (int idx = t; idx < 32; idx += bs) {
        g_wt[A_GLOB_B + idx] = glob_b[idx];
        g_wt[A_AGGW + idx]   = aggw_w[idx];
    }
    for (int idx = t; idx < 16 * 32; idx += bs) {
        int j = idx / 32, k = idx % 32;
        g_wt[A_FC_WT + k * 16 + j] = fc_w[idx];
    }
    for (int idx = t; idx < 16; idx += bs) g_wt[A_FC_B + idx] = fc_b[idx];
    for (int idx = t; idx < 64 * 24; idx += bs) {
        int j = idx / 24, k = idx % 24;
        g_wt[A_LR0_WT + k * 64 + j] = lr0_w[idx];
    }
    for (int idx = t; idx < 64; idx += bs) {
        g_wt[A_LR0_B + idx]   = lr0_b[idx];
        g_wt[A_SIGMA_W + idx] = sigma_w[idx];
        g_wt[GB_BASE + B_C1B + idx] = col1_b[idx];
        g_wt[GB_BASE + B_C2W + idx] = col2_w[idx];
    }
    for (int idx = t; idx < 64 * 111; idx += bs) {
        int j = idx / 111, k = idx % 111;
        g_wt[GB_BASE + B_C1WT + k * 64 + j] = col1_w[idx];
    }
    for (int idx = t; idx < 76; idx += bs) {
        int j = idx / 4, k = idx % 4;
        g_wt[A_VIEW_WT + k * 19 + j] = view_w[idx];
    }
    for (int idx = t; idx < 19; idx += bs) g_wt[A_VIEW_B + idx] = view_b[idx];
    if (t == 0) {
        g_wt[A_SC + 0] = aggw_b[0];
        g_wt[A_SC + 1] = sigma_b[0];
        g_wt[GB_BASE + B_C2B] = col2_b[0];
    }
}

// ---------------- input transpose: [rows][cols] -> [cols][rows] ----------------
__global__ void transpose_kernel(const float* __restrict__ in, float* __restrict__ outp,
                                 int rows, int cols) {
    __shared__ float tile[32][33];
    const int c0 = blockIdx.y * 32;
    const long long r0 = (long long)blockIdx.x * 32;
    const int tx = threadIdx.x, ty = threadIdx.y;
#pragma unroll
    for (int i = 0; i < 32; i += 8) {
        long long r = r0 + ty + i;
        int c = c0 + tx;
        if (r < rows && c < cols) tile[ty + i][tx] = in[r * cols + c];
    }
    __syncthreads();
#pragma unroll
    for (int i = 0; i < 32; i += 8) {
        int c = c0 + ty + i;
        long long r = r0 + tx;
        if (r < rows && c < cols) outp[(size_t)c * rows + r] = tile[tx][ty + i];
    }
}

// ---------------- main kernel ----------------
#define TB 128
#define PTSB 256   // points per block (P=2, adjacent pairs)

__global__ void __launch_bounds__(TB, 3)
nerf_main(const float* __restrict__ vox, float* __restrict__ out, int N) {
    extern __shared__ char dynsmem[];
    ull* sbuf = (ull*)dynsmem;                // 32KB: gf_base spill (phase A/B)
    __half2* h2buf = (__half2*)dynsmem;       // 32KB: x spill [k][t] (lr0->col1)
    __shared__ __align__(16) float sov[B_TOTAL];   // weight overlay (28.9KB)
    const float* sw = sov;

    // stage-1 weights
    for (int idx = threadIdx.x; idx < A_TOTAL; idx += TB) sov[idx] = g_wt[idx];
    __syncthreads();

    const int t = threadIdx.x;
    const int base = blockIdx.x * PTSB;
    const int pt0 = base + 2 * t;       // even; pt1 = pt0 + 1
    const int pt1 = pt0 + 1;
    const bool vld = pt0 < N;           // N even
    const size_t pb = (size_t)(vld ? pt0 : 0);
    const size_t sN = (size_t)N;

#define IN2(f) __ldg(reinterpret_cast<const ull*>(&g_T[(size_t)(f) * sN + pb]))

    // ============ Phase A: dirs, stats, gf_base (spilled to sbuf) ============
    ull dirs[4][4];
#pragma unroll
    for (int s = 0; s < 4; s++)
#pragma unroll
        for (int c = 0; c < 4; c++) dirs[s][c] = IN2(s * 23 + 19 + c);

    {
        ull gfb0[16], gfb1[16];
        LOADB16(gfb0, A_GLOB_B);
#pragma unroll
        for (int q = 0; q < 16; q++) gfb1[q] = gfb0[q];

        const ull c4n = pack2(-4.0f);
        const ull third = pack2(1.0f / 3.0f);
        const ull quarter = pack2(0.25f);

#pragma unroll 2
        for (int k = 0; k < 19; k++) {
            ull sum2 = 0ull, sq2 = 0ull;
#pragma unroll
            for (int s = 0; s < 4; s++) {
                ull a = pack2(sw[A_VIEW_B + k]);
                a = ffma2(pack2(sw[A_VIEW_WT + 0 * 19 + k]), dirs[s][0], a);
                a = ffma2(pack2(sw[A_VIEW_WT + 1 * 19 + k]), dirs[s][1], a);
                a = ffma2(pack2(sw[A_VIEW_WT + 2 * 19 + k]), dirs[s][2], a);
                a = ffma2(pack2(sw[A_VIEW_WT + 3 * 19 + k]), dirs[s][3], a);
                a = relu2(a);
                ull f = fadd2(IN2(s * 23 + k), a);
                sum2 = fadd2(sum2, f);
                sq2 = ffma2(f, f, sq2);
            }
            ull m2 = fmul2(sum2, quarter);
            ull vr2 = fmul2(ffma2(m2, fmul2(m2, c4n), sq2), third);
            float2 mf = unpack2(m2), vf = unpack2(vr2);

            ull x0 = pack2(vf.x), x1 = pack2(vf.y);
            ACC16(gfb0, x0, A_GLOB_WT + (19 + k) * 32);
            ACC16(gfb1, x1, A_GLOB_WT + (19 + k) * 32);
            x0 = pack2(mf.x); x1 = pack2(mf.y);
            ACC16(gfb0, x0, A_GLOB_WT + (38 + k) * 32);
            ACC16(gfb1, x1, A_GLOB_WT + (38 + k) * 32);
        }
#pragma unroll
        for (int q = 0; q < 16; q++) {
            sbuf[q * 256 + t] = gfb0[q];
            sbuf[q * 256 + 128 + t] = gfb1[q];
        }
    }

    // ============ Phase B: per-view glob + online softmax agg ============
    ull num0[16], num1[16];
#pragma unroll
    for (int q = 0; q < 16; q++) { num0[q] = 0ull; num1[q] = 0ull; }
    float dsum0 = 0.0f, dsum1 = 0.0f, mmax0 = -1e30f, mmax1 = -1e30f;
    const float aggb = sw[A_SC + 0];

#pragma unroll
    for (int s = 0; s < 4; s++) {
        ull gf0[16], gf1[16];
#pragma unroll
        for (int q = 0; q < 16; q++) {
            gf0[q] = sbuf[q * 256 + t];
            gf1[q] = sbuf[q * 256 + 128 + t];
        }
#pragma unroll 2
        for (int k = 0; k < 19; k++) {
            ull a = pack2(sw[A_VIEW_B + k]);
            a = ffma2(pack2(sw[A_VIEW_WT + 0 * 19 + k]), dirs[s][0], a);
            a = ffma2(pack2(sw[A_VIEW_WT + 1 * 19 + k]), dirs[s][1], a);
            a = ffma2(pack2(sw[A_VIEW_WT + 2 * 19 + k]), dirs[s][2], a);
            a = ffma2(pack2(sw[A_VIEW_WT + 3 * 19 + k]), dirs[s][3], a);
            a = relu2(a);
            ull f = fadd2(IN2(s * 23 + k), a);
            float2 fi = unpack2(f);
            ull x0 = pack2(fi.x), x1 = pack2(fi.y);
            ACC16(gf0, x0, A_GLOB_WT + k * 32);
            ACC16(gf1, x1, A_GLOB_WT + k * 32);
        }
        ull la0 = 0ull, la1 = 0ull;
        {
            const ulonglong2* aw = reinterpret_cast<const ulonglong2*>(sw + A_AGGW);
#pragma unroll
            for (int q2 = 0; q2 < 8; q2++) {
                ulonglong2 a2 = aw[q2];
                gf0[2 * q2] = relu2(gf0[2 * q2]);
                gf0[2 * q2 + 1] = relu2(gf0[2 * q2 + 1]);
                gf1[2 * q2] = relu2(gf1[2 * q2]);
                gf1[2 * q2 + 1] = relu2(gf1[2 * q2 + 1]);
                la0 = ffma2(a2.x, gf0[2 * q2], la0);
                la0 = ffma2(a2.y, gf0[2 * q2 + 1], la0);
                la1 = ffma2(a2.x, gf1[2 * q2], la1);
                la1 = ffma2(a2.y, gf1[2 * q2 + 1], la1);
            }
        }
        float2 lf0 = unpack2(la0), lf1 = unpack2(la1);
        float l0 = fmaxf(lf0.x + lf0.y + aggb, 0.0f);
        float l1 = fmaxf(lf1.x + lf1.y + aggb, 0.0f);

        if (l0 > mmax0) {
            float c = __expf(mmax0 - l0); ull c2 = pack2(c);
            dsum0 *= c;
#pragma unroll
            for (int q = 0; q < 16; q++) num0[q] = fmul2(num0[q], c2);
            mmax0 = l0;
        }
        {
            float e = __expf(l0 - mmax0); dsum0 += e; ull e2 = pack2(e);
#pragma unroll
            for (int q = 0; q < 16; q++) num0[q] = ffma2(gf0[q], e2, num0[q]);
        }
        if (l1 > mmax1) {
            float c = __expf(mmax1 - l1); ull c2 = pack2(c);
            dsum1 *= c;
#pragma unroll
            for (int q = 0; q < 16; q++) num1[q] = fmul2(num1[q], c2);
            mmax1 = l1;
        }
        {
            float e = __expf(l1 - mmax1); dsum1 += e; ull e2 = pack2(e);
#pragma unroll
            for (int q = 0; q < 16; q++) num1[q] = ffma2(gf1[q], e2, num1[q]);
        }
    }

    // ============ fc: 32 -> 16, build vif[2][24] ============
    float vif0[24], vif1[24];
    {
        float inv0 = 1.0f / dsum0, inv1 = 1.0f / dsum1;
        ull fa0[8], fa1[8];
        LOADB8(fa0, A_FC_B);
#pragma unroll
        for (int q = 0; q < 8; q++) fa1[q] = fa0[q];
#pragma unroll 4
        for (int k = 0; k < 32; k++) {
            ull x0 = pack2(halfOf(num0[k >> 1], k & 1) * inv0);
            ull x1 = pack2(halfOf(num1[k >> 1], k & 1) * inv1);
            ACC8(fa0, x0, A_FC_WT + k * 16);
            ACC8(fa1, x1, A_FC_WT + k * 16);
        }
        const float4* vp4 = reinterpret_cast<const float4*>(vox + pb * 8);
        float4 va = __ldg(vp4),     vb = __ldg(vp4 + 1);
        float4 vc = __ldg(vp4 + 2), vd = __ldg(vp4 + 3);
        vif0[0] = va.x; vif0[1] = va.y; vif0[2] = va.z; vif0[3] = va.w;
        vif0[4] = vb.x; vif0[5] = vb.y; vif0[6] = vb.z; vif0[7] = vb.w;
        vif1[0] = vc.x; vif1[1] = vc.y; vif1[2] = vc.z; vif1[3] = vc.w;
        vif1[4] = vd.x; vif1[5] = vd.y; vif1[6] = vd.z; vif1[7] = vd.w;
#pragma unroll
        for (int j = 0; j < 16; j++) {
            vif0[8 + j] = fmaxf(halfOf(fa0[j >> 1], j & 1), 0.0f);
            vif1[8 + j] = fmaxf(halfOf(fa1[j >> 1], j & 1), 0.0f);
        }
    }

    // ======= lr0: 24 -> 64 (two j-tiles), relu, sigma, x -> h2buf (fp16) =======
    ull siga0 = 0ull, siga1 = 0ull;
#pragma unroll
    for (int jt = 0; jt < 2; jt++) {
        const int j0 = jt * 32;
        ull xa0[16], xa1[16];
        LOADB16(xa0, A_LR0_B + j0);
#pragma unroll
        for (int q = 0; q < 16; q++) xa1[q] = xa0[q];
#pragma unroll 4
        for (int k = 0; k < 24; k++) {
            ull x0 = pack2(vif0[k]);
            ull x1 = pack2(vif1[k]);
            ACC16(xa0, x0, A_LR0_WT + k * 64 + j0);
            ACC16(xa1, x1, A_LR0_WT + k * 64 + j0);
        }
        const ulonglong2* swg = reinterpret_cast<const ulonglong2*>(sw + A_SIGMA_W + j0);
#pragma unroll
        for (int q2 = 0; q2 < 8; q2++) {
            ulonglong2 w = swg[q2];
            ull r0a = relu2(xa0[2 * q2]);
            ull r0b = relu2(xa0[2 * q2 + 1]);
            ull r1a = relu2(xa1[2 * q2]);
            ull r1b = relu2(xa1[2 * q2 + 1]);
            siga0 = ffma2(w.x, r0a, siga0);
            siga0 = ffma2(w.y, r0b, siga0);
            siga1 = ffma2(w.x, r1a, siga1);
            siga1 = ffma2(w.y, r1b, siga1);
            int j = j0 + 4 * q2;
            float2 fa = unpack2(r0a), fb = unpack2(r0b);   // x0[j..j+3]
            float2 ga = unpack2(r1a), gb = unpack2(r1b);   // x1[j..j+3]
            h2buf[(j + 0) * 128 + t] = __floats2half2_rn(fa.x, ga.x);
            h2buf[(j + 1) * 128 + t] = __floats2half2_rn(fa.y, ga.y);
            h2buf[(j + 2) * 128 + t] = __floats2half2_rn(fb.x, gb.x);
            h2buf[(j + 3) * 128 + t] = __floats2half2_rn(fb.y, gb.y);
        }
    }
    float sig0, sig1;
    {
        float2 s0 = unpack2(siga0), s1 = unpack2(siga1);
        float l0 = s0.x + s0.y + sw[A_SC + 1];
        float l1 = s1.x + s1.y + sw[A_SC + 1];
        sig0 = (l0 > 20.0f) ? l0 : log1pf(expf(l0));
        sig1 = (l1 > 20.0f) ? l1 : log1pf(expf(l1));
    }

    // ============ weight overlay swap: stage-2 (col1/col2) ============
    __syncthreads();
    for (int idx = threadIdx.x; idx < B_TOTAL; idx += TB) sov[idx] = g_wt[GB_BASE + idx];
    __syncthreads();

    // ============ col1: 4 x 16-j tiles + col2 partial logits ============
    ull lacc0[4], lacc1[4];
#pragma unroll
    for (int s = 0; s < 4; s++) { lacc0[s] = 0ull; lacc1[s] = 0ull; }

#pragma unroll 1
    for (int jt = 0; jt < 4; jt++) {
        const int j0 = jt * 16;
        ull ba0[8], ba1[8];
        LOADB8(ba0, B_C1B + j0);
#pragma unroll
        for (int q = 0; q < 8; q++) ba1[q] = ba0[q];

        // x rows (k = 0..63) from fp16 spill
#pragma unroll 4
        for (int k = 0; k < 64; k++) {
            float2 xv = __half22float2(h2buf[k * 128 + t]);
            ull x0 = pack2(xv.x);
            ull x1 = pack2(xv.y);
            ACC8(ba0, x0, B_C1WT + k * 64 + j0);
            ACC8(ba1, x1, B_C1WT + k * 64 + j0);
        }
        // vif rows (k = 64..87)
#pragma unroll 4
        for (int k = 0; k < 24; k++) {
            ull x0 = pack2(vif0[k]);
            ull x1 = pack2(vif1[k]);
            ACC8(ba0, x0, B_C1WT + (64 + k) * 64 + j0);
            ACC8(ba1, x1, B_C1WT + (64 + k) * 64 + j0);
        }
        // per-view rows (k = 88..110) + col2 partial dot
#pragma unroll
        for (int s = 0; s < 4; s++) {
            ull va0[8], va1[8];
#pragma unroll
            for (int q = 0; q < 8; q++) { va0[q] = ba0[q]; va1[q] = ba1[q]; }
#pragma unroll 4
            for (int k = 0; k < 23; k++) {
                float2 fv = unpack2(IN2(s * 23 + k));
                ull x0 = pack2(fv.x);
                ull x1 = pack2(fv.y);
                ACC8(va0, x0, B_C1WT + (88 + k) * 64 + j0);
                ACC8(va1, x1, B_C1WT + (88 + k) * 64 + j0);
            }
            const ulonglong2* cw =
                reinterpret_cast<const ulonglong2*>(sw + B_C2W + j0);
#pragma unroll
            for (int q2 = 0; q2 < 4; q2++) {
                ulonglong2 w = cw[q2];
                lacc0[s] = ffma2(w.x, relu2(va0[2 * q2]), lacc0[s]);
                lacc0[s] = ffma2(w.y, relu2(va0[2 * q2 + 1]), lacc0[s]);
                lacc1[s] = ffma2(w.x, relu2(va1[2 * q2]), lacc1[s]);
                lacc1[s] = ffma2(w.y, relu2(va1[2 * q2 + 1]), lacc1[s]);
            }
        }
    }

    // ============ color softmax + output ============
    const float col2b = sw[B_C2B];
    float l0[4], l1[4];
#pragma unroll
    for (int s = 0; s < 4; s++) {
        float2 a = unpack2(lacc0[s]);
        float2 b = unpack2(lacc1[s]);
        l0[s] = fmaxf(a.x + a.y + col2b, 0.0f);
        l1[s] = fmaxf(b.x + b.y + col2b, 0.0f);
    }
    float m0 = fmaxf(fmaxf(l0[0], l0[1]), fmaxf(l0[2], l0[3]));
    float m1 = fmaxf(fmaxf(l1[0], l1[1]), fmaxf(l1[2], l1[3]));
    float cn0[3] = {0, 0, 0}, cn1[3] = {0, 0, 0}, cd0 = 0.0f, cd1 = 0.0f;
#pragma unroll
    for (int s = 0; s < 4; s++) {
        float e0 = __expf(l0[s] - m0);
        float e1 = __expf(l1[s] - m1);
        cd0 += e0; cd1 += e1;
#pragma unroll
        for (int c = 0; c < 3; c++) {
            float2 rgb = unpack2(IN2(s * 23 + 16 + c));
            cn0[c] += rgb.x * e0;
            cn1[c] += rgb.y * e1;
        }
    }
    if (vld) {
        float inv0 = 1.0f / cd0;
        float inv1 = 1.0f / cd1;
        float4 o0 = make_float4(cn0[0] * inv0, cn0[1] * inv0, cn0[2] * inv0, sig0);
        float4 o1 = make_float4(cn1[0] * inv1, cn1[1] * inv1, cn1[2] * inv1, sig1);
        reinterpret_cast<float4*>(out)[pt0] = o0;
        reinterpret_cast<float4*>(out)[pt1] = o1;
    }
#undef IN2
}

extern "C" void kernel_launch(void* const* d_in, const int* in_sizes, int n_in,
                              void* d_out, int out_size) {
    const float* vox     = (const float*)d_in[0];
    const float* ifrd    = (const float*)d_in[1];
    const float* view_w  = (const float*)d_in[2];
    const float* view_b  = (const float*)d_in[3];
    const float* glob_w  = (const float*)d_in[4];
    const float* glob_b  = (const float*)d_in[5];
    const float* aggw_w  = (const float*)d_in[6];
    const float* aggw_b  = (const float*)d_in[7];
    const float* fc_w    = (const float*)d_in[8];
    const float* fc_b    = (const float*)d_in[9];
    const float* lr0_w   = (const float*)d_in[10];
    const float* lr0_b   = (const float*)d_in[11];
    const float* sigma_w = (const float*)d_in[12];
    const float* sigma_b = (const float*)d_in[13];
    const float* col1_w  = (const float*)d_in[14];
    const float* col1_b  = (const float*)d_in[15];
    const float* col2_w  = (const float*)d_in[16];
    const float* col2_b  = (const float*)d_in[17];
    float* out = (float*)d_out;

    int N = in_sizes[0] / 8;
    if (N > NMAX) N = NMAX;

    cudaFuncSetAttribute(nerf_main, cudaFuncAttributeMaxDynamicSharedMemorySize, 32768);

    float* tptr = nullptr;
    cudaGetSymbolAddress((void**)&tptr, g_T);

    prep_kernel<<<1, 256>>>(view_w, view_b, glob_w, glob_b, aggw_w, aggw_b,
                            fc_w, fc_b, lr0_w, lr0_b, sigma_w, sigma_b,
                            col1_w, col1_b, col2_w, col2_b);

    dim3 tb(32, 8);
    dim3 tg1((N + 31) / 32, (92 + 31) / 32);
    transpose_kernel<<<tg1, tb>>>(ifrd, tptr, N, 92);

    int blocks = (N + PTSB - 1) / PTSB;
    nerf_main<<<blocks, TB, 32768>>>(vox, out, N);
}